// round 6
// baseline (speedup 1.0000x reference)
#include <cuda_runtime.h>
#include <math.h>

// Problem shape (fixed by setup_inputs)
#define SDIM 2048
#define RDIM 512
#define CDIM 64
#define NSBLK 32           // SDIM/64 blocks per r in kernel A

// ---------------- device scratch (no allocs allowed) ----------------
static __device__ float g_poolp[RDIM][NSBLK][64];       // per-(r, sblk) pool partials
static __device__ float g_msump[RDIM][NSBLK];           // per-(r, sblk) mask-sum partials
static __device__ float g_kv[(size_t)RDIM * SDIM * 16]; // per (r,s): k[0..7], v[0..7]
static __device__ float g_ovec[RDIM * CDIM];            // per r: o[h*8+ch]

// ---------------- f32x2 helpers --------------------------------------
__device__ __forceinline__ unsigned long long ffma2(unsigned long long a,
                                                    unsigned long long b,
                                                    unsigned long long c) {
    unsigned long long d;
    asm("fma.rn.f32x2 %0, %1, %2, %3;" : "=l"(d) : "l"(a), "l"(b), "l"(c));
    return d;
}
__device__ __forceinline__ unsigned long long splat2(float x) {
    unsigned long long d;
    asm("mov.b64 %0, {%1, %1};" : "=l"(d) : "f"(x));
    return d;
}
__device__ __forceinline__ float2 unpk(unsigned long long v) {
    float2 f;
    asm("mov.b64 {%0, %1}, %2;" : "=f"(f.x), "=f"(f.y) : "l"(v));
    return f;
}
__device__ __forceinline__ float sigm(float x) {
    float t = __expf(-x);
    return __fdividef(1.f, 1.f + t);
}

// ---------------- kernel A: LN + masked pool + K/V -------------------
// grid (NSBLK, RDIM), 256 threads. Each block: one r, 64 consecutive s rows.
__global__ void __launch_bounds__(256) k_pool_kv(
    const float* __restrict__ m, const float* __restrict__ mask,
    const float* __restrict__ ln_w, const float* __restrict__ ln_b,
    const float* __restrict__ wk, const float* __restrict__ wv)
{
    __shared__ float s_xnT[CDIM][68];   // transposed: [c][row], padded
    __shared__ float s_wkv[CDIM][16];   // [c][j]: j<8 -> wk, j>=8 -> wv
    __shared__ float s_pool[8][64];
    __shared__ float s_ms[8];

    const int r   = blockIdx.y;
    const int s0  = blockIdx.x * 64;
    const int tid = threadIdx.x;
    const int lane = tid & 31;
    const int w    = tid >> 5;

    for (int i = tid; i < CDIM * 8; i += 256) {
        s_wkv[i >> 3][(i & 7)]     = wk[i];
        s_wkv[i >> 3][(i & 7) + 8] = wv[i];
    }

    const float lw0 = ln_w[lane], lw1 = ln_w[lane + 32];
    const float lb0 = ln_b[lane], lb1 = ln_b[lane + 32];

    float p0 = 0.f, p1 = 0.f, pm = 0.f;
    #pragma unroll
    for (int i = 0; i < 8; ++i) {
        const int row = w * 8 + i;
        const int s   = s0 + row;
        const float* mp = m + ((size_t)s * RDIM + r) * CDIM;
        float x0 = mp[lane];
        float x1 = mp[lane + 32];
        float mv = __ldg(&mask[s * RDIM + r]);

        float sum = x0 + x1;
        #pragma unroll
        for (int o = 16; o; o >>= 1) sum += __shfl_xor_sync(0xffffffffu, sum, o);
        float mu = sum * (1.f / 64.f);
        float d0 = x0 - mu, d1 = x1 - mu;
        float vv = d0 * d0 + d1 * d1;
        #pragma unroll
        for (int o = 16; o; o >>= 1) vv += __shfl_xor_sync(0xffffffffu, vv, o);
        float rstd = rsqrtf(vv * (1.f / 64.f) + 1e-5f);
        float xn0 = d0 * rstd * lw0 + lb0;
        float xn1 = d1 * rstd * lw1 + lb1;

        s_xnT[lane][row]      = xn0;
        s_xnT[lane + 32][row] = xn1;
        p0 += xn0 * mv;
        p1 += xn1 * mv;
        pm += mv;   // NOTE: identical across all 32 lanes (same rows)
    }
    s_pool[w][lane]      = p0;
    s_pool[w][lane + 32] = p1;
    // pm is already the warp's 8-row mask sum, replicated per lane: take ONE copy.
    if (lane == 0) s_ms[w] = pm;
    __syncthreads();

    if (tid < 64) {
        float a = 0.f;
        #pragma unroll
        for (int k = 0; k < 8; ++k) a += s_pool[k][tid];
        g_poolp[r][blockIdx.x][tid] = a;
    }
    if (tid == 0) {
        float a = 0.f;
        #pragma unroll
        for (int k = 0; k < 8; ++k) a += s_ms[k];
        g_msump[r][blockIdx.x] = a;
    }

    // K/V GEMM: [64 rows x 64 c] @ [64 c x 16 j]
    const int rg = lane & 1;          // row sub-group
    const int cg = lane >> 1;         // output col 0..15
    const int row0 = w * 8 + rg * 4;
    float a0 = 0.f, a1 = 0.f, a2 = 0.f, a3 = 0.f;
    #pragma unroll 8
    for (int c = 0; c < 64; ++c) {
        float4 xv = *(const float4*)&s_xnT[c][row0];
        float ww  = s_wkv[c][cg];
        a0 += xv.x * ww; a1 += xv.y * ww; a2 += xv.z * ww; a3 += xv.w * ww;
    }
    float* kvp = g_kv + ((size_t)r * SDIM + s0 + row0) * 16 + cg;
    kvp[0]  = a0;
    kvp[16] = a1;
    kvp[32] = a2;
    kvp[48] = a3;
}

// ---------------- kernel B: pool reduce, q, softmax over S, o --------
// grid (RDIM), 256 threads: warp h handles head h; lane strides over s.
__global__ void __launch_bounds__(256) k_attn(
    const float* __restrict__ mask, const float* __restrict__ wq)
{
    const int r   = blockIdx.x;
    const int tid = threadIdx.x;
    const int lane = tid & 31;
    const int h    = tid >> 5;

    __shared__ float s_p[64];
    __shared__ float s_red[256];
    __shared__ float s_minv;

    if (tid < 32) {
        float mm = g_msump[r][lane];
        #pragma unroll
        for (int o = 16; o; o >>= 1) mm += __shfl_xor_sync(0xffffffffu, mm, o);
        if (lane == 0) s_minv = __fdividef(1.f, mm + 1e-10f);
    }
    {
        int c = tid & 63, gp = tid >> 6;
        float a = 0.f;
        #pragma unroll
        for (int k = 0; k < 8; ++k) a += g_poolp[r][gp * 8 + k][c];
        s_red[tid] = a;
    }
    __syncthreads();
    if (tid < 64)
        s_p[tid] = (s_red[tid] + s_red[tid + 64] + s_red[tid + 128] + s_red[tid + 192]) * s_minv;
    __syncthreads();

    // q[h][0..7] = (pool @ wq) * 8^-0.5
    float q[8];
    float pc0 = s_p[lane], pc1 = s_p[lane + 32];
    #pragma unroll
    for (int j = 0; j < 8; ++j)
        q[j] = pc0 * wq[lane * 64 + h * 8 + j] + pc1 * wq[(lane + 32) * 64 + h * 8 + j];
    #pragma unroll
    for (int o = 16; o; o >>= 1) {
        #pragma unroll
        for (int j = 0; j < 8; ++j) q[j] += __shfl_xor_sync(0xffffffffu, q[j], o);
    }
    #pragma unroll
    for (int j = 0; j < 8; ++j) q[j] *= 0.35355339059327373f;

    const float LOG2E = 1.4426950408889634f;
    float M = -1e30f, L = 0.f;
    float acc[8];
    #pragma unroll
    for (int j = 0; j < 8; ++j) acc[j] = 0.f;

    for (int t = 0; t < SDIM / 32; ++t) {
        int s = t * 32 + lane;
        const float4* kv = (const float4*)(g_kv + ((size_t)r * SDIM + s) * 16);
        float4 k0 = kv[0], k1 = kv[1];
        float4 v0 = kv[2], v1 = kv[3];
        float mv = __ldg(&mask[s * RDIM + r]);
        float logit = q[0]*k0.x + q[1]*k0.y + q[2]*k0.z + q[3]*k0.w
                    + q[4]*k1.x + q[5]*k1.y + q[6]*k1.z + q[7]*k1.w
                    + 1e9f * (mv - 1.f);
        float nM = fmaxf(M, logit);
        float sc = exp2f((M - nM) * LOG2E);
        float p  = exp2f((logit - nM) * LOG2E);
        L = L * sc + p;
        acc[0] = acc[0]*sc + p*v0.x; acc[1] = acc[1]*sc + p*v0.y;
        acc[2] = acc[2]*sc + p*v0.z; acc[3] = acc[3]*sc + p*v0.w;
        acc[4] = acc[4]*sc + p*v1.x; acc[5] = acc[5]*sc + p*v1.y;
        acc[6] = acc[6]*sc + p*v1.z; acc[7] = acc[7]*sc + p*v1.w;
        M = nM;
    }
    // merge lanes
    float Mm = M;
    #pragma unroll
    for (int o = 16; o; o >>= 1) Mm = fmaxf(Mm, __shfl_xor_sync(0xffffffffu, Mm, o));
    float sc = exp2f((M - Mm) * LOG2E);
    L *= sc;
    #pragma unroll
    for (int j = 0; j < 8; ++j) acc[j] *= sc;
    #pragma unroll
    for (int o = 16; o; o >>= 1) {
        L += __shfl_xor_sync(0xffffffffu, L, o);
        #pragma unroll
        for (int j = 0; j < 8; ++j) acc[j] += __shfl_xor_sync(0xffffffffu, acc[j], o);
    }
    if (lane == 0) {
        float inv = 1.f / L;
        #pragma unroll
        for (int j = 0; j < 8; ++j) g_ovec[r * 64 + h * 8 + j] = acc[j] * inv;
    }
}

// ---------------- kernel C: LN -> gate GEMM -> output GEMM -----------
// grid (SDIM/128, RDIM), 256 threads, dynamic smem. f32x2 packed math.
#define XPAD 132
#define GPAD 65
__global__ void __launch_bounds__(256, 2) k_out(
    const float* __restrict__ m,
    const float* __restrict__ ln_w, const float* __restrict__ ln_b,
    const float* __restrict__ wg, const float* __restrict__ bg,
    const float* __restrict__ wo, const float* __restrict__ bo,
    float* __restrict__ out)
{
    extern __shared__ float sm[];
    float* s_xnT = sm;                       // [64][XPAD]  c-major
    float* s_g   = sm + 64 * XPAD;           // [128][GPAD] row-major
    float* s_wg  = s_g + 128 * GPAD;         // [c*64+j]
    float* s_wo  = s_wg + 64 * 64;           // folded o[j]*wo[j][c]
    float* s_bg  = s_wo + 64 * 64;           // [64]

    const int r   = blockIdx.y;
    const int s0  = blockIdx.x * 128;
    const int tid = threadIdx.x;
    const int lane = tid & 31;
    const int w    = tid >> 5;

    // weights
    const float* ov = g_ovec + r * 64;
    {
        const float4* wg4 = (const float4*)wg;
        const float4* wo4 = (const float4*)wo;
        float4* swg4 = (float4*)s_wg;
        float4* swo4 = (float4*)s_wo;
        for (int i = tid; i < 1024; i += 256) {
            swg4[i] = wg4[i];
            float s = __ldg(&ov[i >> 4]);
            float4 v = wo4[i];
            v.x *= s; v.y *= s; v.z *= s; v.w *= s;
            swo4[i] = v;
        }
        if (tid < 16) ((float4*)s_bg)[tid] = ((const float4*)bg)[tid];
    }

    // LayerNorm: warp per row, 16 rows per warp
    const float lw0 = ln_w[lane], lw1 = ln_w[lane + 32];
    const float lb0 = ln_b[lane], lb1 = ln_b[lane + 32];
    #pragma unroll
    for (int i = 0; i < 16; ++i) {
        const int row = w * 16 + i;
        const int s   = s0 + row;
        const float* mp = m + ((size_t)s * RDIM + r) * CDIM;
        float x0 = mp[lane];
        float x1 = mp[lane + 32];
        float sum = x0 + x1;
        #pragma unroll
        for (int o = 16; o; o >>= 1) sum += __shfl_xor_sync(0xffffffffu, sum, o);
        float mu = sum * (1.f / 64.f);
        float d0 = x0 - mu, d1 = x1 - mu;
        float vv = d0 * d0 + d1 * d1;
        #pragma unroll
        for (int o = 16; o; o >>= 1) vv += __shfl_xor_sync(0xffffffffu, vv, o);
        float rstd = rsqrtf(vv * (1.f / 64.f) + 1e-5f);
        s_xnT[lane * XPAD + row]        = d0 * rstd * lw0 + lb0;
        s_xnT[(lane + 32) * XPAD + row] = d1 * rstd * lw1 + lb1;
    }
    __syncthreads();

    const int rg   = tid >> 3;      // 0..31
    const int cg   = tid & 7;       // 0..7
    const int row0 = rg * 4;
    const int j0   = cg * 8;

    // GEMM1: G = sigmoid(XN @ wg + bg)  -- f32x2, 4 rows x 8 cols per thread
    unsigned long long acc1[4][4];
    #pragma unroll
    for (int a = 0; a < 4; ++a)
        #pragma unroll
        for (int b = 0; b < 4; ++b) acc1[a][b] = 0ull;

    #pragma unroll 4
    for (int c = 0; c < 64; ++c) {
        float4 xv = *(const float4*)&s_xnT[c * XPAD + row0];
        ulonglong2 wa = *(const ulonglong2*)&s_wg[c * 64 + j0];
        ulonglong2 wb = *(const ulonglong2*)&s_wg[c * 64 + j0 + 4];
        unsigned long long sx0 = splat2(xv.x), sx1 = splat2(xv.y);
        unsigned long long sx2 = splat2(xv.z), sx3 = splat2(xv.w);
        acc1[0][0] = ffma2(sx0, wa.x, acc1[0][0]);
        acc1[0][1] = ffma2(sx0, wa.y, acc1[0][1]);
        acc1[0][2] = ffma2(sx0, wb.x, acc1[0][2]);
        acc1[0][3] = ffma2(sx0, wb.y, acc1[0][3]);
        acc1[1][0] = ffma2(sx1, wa.x, acc1[1][0]);
        acc1[1][1] = ffma2(sx1, wa.y, acc1[1][1]);
        acc1[1][2] = ffma2(sx1, wb.x, acc1[1][2]);
        acc1[1][3] = ffma2(sx1, wb.y, acc1[1][3]);
        acc1[2][0] = ffma2(sx2, wa.x, acc1[2][0]);
        acc1[2][1] = ffma2(sx2, wa.y, acc1[2][1]);
        acc1[2][2] = ffma2(sx2, wb.x, acc1[2][2]);
        acc1[2][3] = ffma2(sx2, wb.y, acc1[2][3]);
        acc1[3][0] = ffma2(sx3, wa.x, acc1[3][0]);
        acc1[3][1] = ffma2(sx3, wa.y, acc1[3][1]);
        acc1[3][2] = ffma2(sx3, wb.x, acc1[3][2]);
        acc1[3][3] = ffma2(sx3, wb.y, acc1[3][3]);
    }
    #pragma unroll
    for (int i = 0; i < 4; ++i) {
        float* gp = &s_g[(row0 + i) * GPAD + j0];
        #pragma unroll
        for (int p = 0; p < 4; ++p) {
            float2 y = unpk(acc1[i][p]);
            gp[2 * p]     = sigm(y.x + s_bg[j0 + 2 * p]);
            gp[2 * p + 1] = sigm(y.y + s_bg[j0 + 2 * p + 1]);
        }
    }
    __syncthreads();

    // GEMM2: out = G @ (o (.) wo) + bo  -- f32x2
    unsigned long long acc2[4][4];
    #pragma unroll
    for (int a = 0; a < 4; ++a)
        #pragma unroll
        for (int b = 0; b < 4; ++b) acc2[a][b] = 0ull;

    #pragma unroll 4
    for (int j = 0; j < 64; ++j) {
        ulonglong2 wa = *(const ulonglong2*)&s_wo[j * 64 + j0];
        ulonglong2 wb = *(const ulonglong2*)&s_wo[j * 64 + j0 + 4];
        unsigned long long g0 = splat2(s_g[(row0 + 0) * GPAD + j]);
        unsigned long long g1 = splat2(s_g[(row0 + 1) * GPAD + j]);
        unsigned long long g2 = splat2(s_g[(row0 + 2) * GPAD + j]);
        unsigned long long g3 = splat2(s_g[(row0 + 3) * GPAD + j]);
        acc2[0][0] = ffma2(g0, wa.x, acc2[0][0]);
        acc2[0][1] = ffma2(g0, wa.y, acc2[0][1]);
        acc2[0][2] = ffma2(g0, wb.x, acc2[0][2]);
        acc2[0][3] = ffma2(g0, wb.y, acc2[0][3]);
        acc2[1][0] = ffma2(g1, wa.x, acc2[1][0]);
        acc2[1][1] = ffma2(g1, wa.y, acc2[1][1]);
        acc2[1][2] = ffma2(g1, wb.x, acc2[1][2]);
        acc2[1][3] = ffma2(g1, wb.y, acc2[1][3]);
        acc2[2][0] = ffma2(g2, wa.x, acc2[2][0]);
        acc2[2][1] = ffma2(g2, wa.y, acc2[2][1]);
        acc2[2][2] = ffma2(g2, wb.x, acc2[2][2]);
        acc2[2][3] = ffma2(g2, wb.y, acc2[2][3]);
        acc2[3][0] = ffma2(g3, wa.x, acc2[3][0]);
        acc2[3][1] = ffma2(g3, wa.y, acc2[3][1]);
        acc2[3][2] = ffma2(g3, wb.x, acc2[3][2]);
        acc2[3][3] = ffma2(g3, wb.y, acc2[3][3]);
    }

    float4 b0 = *(const float4*)&bo[j0];
    float4 b1 = *(const float4*)&bo[j0 + 4];
    #pragma unroll
    for (int i = 0; i < 4; ++i) {
        const int s = s0 + row0 + i;
        float* op = out + ((size_t)s * RDIM + r) * CDIM + j0;
        float2 o0 = unpk(acc2[i][0]);
        float2 o1 = unpk(acc2[i][1]);
        float2 o2 = unpk(acc2[i][2]);
        float2 o3 = unpk(acc2[i][3]);
        float4 v0 = make_float4(o0.x + b0.x, o0.y + b0.y, o1.x + b0.z, o1.y + b0.w);
        float4 v1 = make_float4(o2.x + b1.x, o2.y + b1.y, o3.x + b1.z, o3.y + b1.w);
        *(float4*)op       = v0;
        *(float4*)(op + 4) = v1;
    }
}

// ---------------------------------------------------------------------
extern "C" void kernel_launch(void* const* d_in, const int* in_sizes, int n_in,
                              void* d_out, int out_size) {
    const float* m    = (const float*)d_in[0];
    const float* mask = (const float*)d_in[1];
    const float* ln_w = (const float*)d_in[2];
    const float* ln_b = (const float*)d_in[3];
    const float* wq   = (const float*)d_in[4];
    const float* wk   = (const float*)d_in[5];
    const float* wv   = (const float*)d_in[6];
    const float* wg   = (const float*)d_in[7];
    const float* bg   = (const float*)d_in[8];
    const float* wo   = (const float*)d_in[9];
    const float* bo   = (const float*)d_in[10];
    float* out = (float*)d_out;

    const int SMEM_C = (64 * XPAD + 128 * GPAD + 2 * 64 * 64 + 64) * (int)sizeof(float); // 100096 B
    cudaFuncSetAttribute(k_out, cudaFuncAttributeMaxDynamicSharedMemorySize, SMEM_C);

    dim3 gA(NSBLK, RDIM);
    k_pool_kv<<<gA, 256>>>(m, mask, ln_w, ln_b, wk, wv);
    k_attn<<<RDIM, 256>>>(mask, wq);
    dim3 gC(SDIM / 128, RDIM);
    k_out<<<gC, 256, SMEM_C>>>(m, ln_w, ln_b, wg, bg, wo, bo, out);
}

// round 8
// speedup vs baseline: 1.6104x; 1.6104x over previous
#include <cuda_runtime.h>
#include <cuda_bf16.h>
#include <math.h>
#include <stdint.h>

// Problem shape (fixed by setup_inputs)
#define SDIM 2048
#define RDIM 512
#define CDIM 64
#define NSBLK 32           // SDIM/64 blocks per r in kernel A

// ---------------- device scratch (no allocs allowed) ----------------
static __device__ float g_poolp[RDIM][NSBLK][64];       // per-(r, sblk) pool partials
static __device__ float g_msump[RDIM][NSBLK];           // per-(r, sblk) mask-sum partials
static __device__ float g_kv[(size_t)RDIM * SDIM * 16]; // per (r,s): k[0..7], v[0..7]
static __device__ float g_ovec[RDIM * CDIM];            // per r: o[h*8+ch]

__device__ __forceinline__ float sigm(float x) {
    float t = __expf(-x);
    return __fdividef(1.f, 1.f + t);
}

// ---------------- kernel A: LN + masked pool + K/V (unchanged, passing) ----
__global__ void __launch_bounds__(256) k_pool_kv(
    const float* __restrict__ m, const float* __restrict__ mask,
    const float* __restrict__ ln_w, const float* __restrict__ ln_b,
    const float* __restrict__ wk, const float* __restrict__ wv)
{
    __shared__ float s_xnT[CDIM][68];
    __shared__ float s_wkv[CDIM][16];
    __shared__ float s_pool[8][64];
    __shared__ float s_ms[8];

    const int r   = blockIdx.y;
    const int s0  = blockIdx.x * 64;
    const int tid = threadIdx.x;
    const int lane = tid & 31;
    const int w    = tid >> 5;

    for (int i = tid; i < CDIM * 8; i += 256) {
        s_wkv[i >> 3][(i & 7)]     = wk[i];
        s_wkv[i >> 3][(i & 7) + 8] = wv[i];
    }

    const float lw0 = ln_w[lane], lw1 = ln_w[lane + 32];
    const float lb0 = ln_b[lane], lb1 = ln_b[lane + 32];

    float p0 = 0.f, p1 = 0.f, pm = 0.f;
    #pragma unroll
    for (int i = 0; i < 8; ++i) {
        const int row = w * 8 + i;
        const int s   = s0 + row;
        const float* mp = m + ((size_t)s * RDIM + r) * CDIM;
        float x0 = mp[lane];
        float x1 = mp[lane + 32];
        float mv = __ldg(&mask[s * RDIM + r]);

        float sum = x0 + x1;
        #pragma unroll
        for (int o = 16; o; o >>= 1) sum += __shfl_xor_sync(0xffffffffu, sum, o);
        float mu = sum * (1.f / 64.f);
        float d0 = x0 - mu, d1 = x1 - mu;
        float vv = d0 * d0 + d1 * d1;
        #pragma unroll
        for (int o = 16; o; o >>= 1) vv += __shfl_xor_sync(0xffffffffu, vv, o);
        float rstd = rsqrtf(vv * (1.f / 64.f) + 1e-5f);
        float xn0 = d0 * rstd * lw0 + lb0;
        float xn1 = d1 * rstd * lw1 + lb1;

        s_xnT[lane][row]      = xn0;
        s_xnT[lane + 32][row] = xn1;
        p0 += xn0 * mv;
        p1 += xn1 * mv;
        pm += mv;
    }
    s_pool[w][lane]      = p0;
    s_pool[w][lane + 32] = p1;
    if (lane == 0) s_ms[w] = pm;
    __syncthreads();

    if (tid < 64) {
        float a = 0.f;
        #pragma unroll
        for (int k = 0; k < 8; ++k) a += s_pool[k][tid];
        g_poolp[r][blockIdx.x][tid] = a;
    }
    if (tid == 0) {
        float a = 0.f;
        #pragma unroll
        for (int k = 0; k < 8; ++k) a += s_ms[k];
        g_msump[r][blockIdx.x] = a;
    }

    const int rg = lane & 1;
    const int cg = lane >> 1;
    const int row0 = w * 8 + rg * 4;
    float a0 = 0.f, a1 = 0.f, a2 = 0.f, a3 = 0.f;
    #pragma unroll 8
    for (int c = 0; c < 64; ++c) {
        float4 xv = *(const float4*)&s_xnT[c][row0];
        float ww  = s_wkv[c][cg];
        a0 += xv.x * ww; a1 += xv.y * ww; a2 += xv.z * ww; a3 += xv.w * ww;
    }
    float* kvp = g_kv + ((size_t)r * SDIM + s0 + row0) * 16 + cg;
    kvp[0]  = a0;
    kvp[16] = a1;
    kvp[32] = a2;
    kvp[48] = a3;
}

// ---------------- kernel B: pool reduce, q, softmax over S, o (unchanged) ----
__global__ void __launch_bounds__(256) k_attn(
    const float* __restrict__ mask, const float* __restrict__ wq)
{
    const int r   = blockIdx.x;
    const int tid = threadIdx.x;
    const int lane = tid & 31;
    const int h    = tid >> 5;

    __shared__ float s_p[64];
    __shared__ float s_red[256];
    __shared__ float s_minv;

    if (tid < 32) {
        float mm = g_msump[r][lane];
        #pragma unroll
        for (int o = 16; o; o >>= 1) mm += __shfl_xor_sync(0xffffffffu, mm, o);
        if (lane == 0) s_minv = __fdividef(1.f, mm + 1e-10f);
    }
    {
        int c = tid & 63, gp = tid >> 6;
        float a = 0.f;
        #pragma unroll
        for (int k = 0; k < 8; ++k) a += g_poolp[r][gp * 8 + k][c];
        s_red[tid] = a;
    }
    __syncthreads();
    if (tid < 64)
        s_p[tid] = (s_red[tid] + s_red[tid + 64] + s_red[tid + 128] + s_red[tid + 192]) * s_minv;
    __syncthreads();

    float q[8];
    float pc0 = s_p[lane], pc1 = s_p[lane + 32];
    #pragma unroll
    for (int j = 0; j < 8; ++j)
        q[j] = pc0 * wq[lane * 64 + h * 8 + j] + pc1 * wq[(lane + 32) * 64 + h * 8 + j];
    #pragma unroll
    for (int o = 16; o; o >>= 1) {
        #pragma unroll
        for (int j = 0; j < 8; ++j) q[j] += __shfl_xor_sync(0xffffffffu, q[j], o);
    }
    #pragma unroll
    for (int j = 0; j < 8; ++j) q[j] *= 0.35355339059327373f;

    const float LOG2E = 1.4426950408889634f;
    float M = -1e30f, L = 0.f;
    float acc[8];
    #pragma unroll
    for (int j = 0; j < 8; ++j) acc[j] = 0.f;

    for (int t = 0; t < SDIM / 32; ++t) {
        int s = t * 32 + lane;
        const float4* kv = (const float4*)(g_kv + ((size_t)r * SDIM + s) * 16);
        float4 k0 = kv[0], k1 = kv[1];
        float4 v0 = kv[2], v1 = kv[3];
        float mv = __ldg(&mask[s * RDIM + r]);
        float logit = q[0]*k0.x + q[1]*k0.y + q[2]*k0.z + q[3]*k0.w
                    + q[4]*k1.x + q[5]*k1.y + q[6]*k1.z + q[7]*k1.w
                    + 1e9f * (mv - 1.f);
        float nM = fmaxf(M, logit);
        float sc = exp2f((M - nM) * LOG2E);
        float p  = exp2f((logit - nM) * LOG2E);
        L = L * sc + p;
        acc[0] = acc[0]*sc + p*v0.x; acc[1] = acc[1]*sc + p*v0.y;
        acc[2] = acc[2]*sc + p*v0.z; acc[3] = acc[3]*sc + p*v0.w;
        acc[4] = acc[4]*sc + p*v1.x; acc[5] = acc[5]*sc + p*v1.y;
        acc[6] = acc[6]*sc + p*v1.z; acc[7] = acc[7]*sc + p*v1.w;
        M = nM;
    }
    float Mm = M;
    #pragma unroll
    for (int o = 16; o; o >>= 1) Mm = fmaxf(Mm, __shfl_xor_sync(0xffffffffu, Mm, o));
    float sc = exp2f((M - Mm) * LOG2E);
    L *= sc;
    #pragma unroll
    for (int j = 0; j < 8; ++j) acc[j] *= sc;
    #pragma unroll
    for (int o = 16; o; o >>= 1) {
        L += __shfl_xor_sync(0xffffffffu, L, o);
        #pragma unroll
        for (int j = 0; j < 8; ++j) acc[j] += __shfl_xor_sync(0xffffffffu, acc[j], o);
    }
    if (lane == 0) {
        float inv = 1.f / L;
        #pragma unroll
        for (int j = 0; j < 8; ++j) g_ovec[r * 64 + h * 8 + j] = acc[j] * inv;
    }
}

// ============ kernel C: HMMA (mma.sync bf16) 3-pass split GEMM ============
// Block: one r, 128 s-rows, 256 threads (8 warps; warp w owns rows w*16..+15).
// GEMM1: XN[128x64] @ wg[64x64] -> sigmoid -> G (overwrites XN tiles)
// GEMM2: G[128x64] @ (ov.*wo)[64x64] + bo -> out
#define AS 72     // bf16 stride for A tiles [128][AS] (144B rows: conflict-free)
#define BS 72     // bf16 stride for B tiles [64][BS]

__device__ __forceinline__ void mma_bf16(float d[4],
    uint32_t a0, uint32_t a1, uint32_t a2, uint32_t a3,
    uint32_t b0, uint32_t b1)
{
    asm volatile(
        "mma.sync.aligned.m16n8k16.row.col.f32.bf16.bf16.f32 "
        "{%0,%1,%2,%3}, {%4,%5,%6,%7}, {%8,%9}, {%0,%1,%2,%3};"
        : "+f"(d[0]), "+f"(d[1]), "+f"(d[2]), "+f"(d[3])
        : "r"(a0), "r"(a1), "r"(a2), "r"(a3), "r"(b0), "r"(b1));
}
__device__ __forceinline__ uint32_t ld32s(const __nv_bfloat16* p) {
    return *(const uint32_t*)p;
}
__device__ __forceinline__ uint32_t pack_hi2(float x, float y) {
    __nv_bfloat16 hx = __float2bfloat16(x), hy = __float2bfloat16(y);
    return (uint32_t)__bfloat16_as_ushort(hx) | ((uint32_t)__bfloat16_as_ushort(hy) << 16);
}
__device__ __forceinline__ uint32_t pack_lo2(float x, float y) {
    __nv_bfloat16 hx = __float2bfloat16(x), hy = __float2bfloat16(y);
    __nv_bfloat16 lx = __float2bfloat16(x - __bfloat162float(hx));
    __nv_bfloat16 ly = __float2bfloat16(y - __bfloat162float(hy));
    return (uint32_t)__bfloat16_as_ushort(lx) | ((uint32_t)__bfloat16_as_ushort(ly) << 16);
}

#define SMC_BYTES (2*128*AS*2 + 4*64*BS*2 + 2*64*4)   // 73728 + 36864(512) -> 74240

__global__ void __launch_bounds__(256) k_out_mma(
    const float* __restrict__ m,
    const float* __restrict__ ln_w, const float* __restrict__ ln_b,
    const float* __restrict__ wg, const float* __restrict__ bg,
    const float* __restrict__ wo, const float* __restrict__ bo,
    float* __restrict__ out)
{
    extern __shared__ __align__(16) uint8_t smraw[];
    __nv_bfloat16* s_ah  = (__nv_bfloat16*)smraw;        // [128][AS] X hi / later G hi
    __nv_bfloat16* s_al  = s_ah  + 128 * AS;             // [128][AS] X lo / later G lo
    __nv_bfloat16* s_b1h = s_al  + 128 * AS;             // [64][BS]  wg^T hi   (n=j, k=c)
    __nv_bfloat16* s_b1l = s_b1h + 64 * BS;
    __nv_bfloat16* s_b2h = s_b1l + 64 * BS;              // [64][BS]  (ov.*wo)^T hi (n=cc, k=j)
    __nv_bfloat16* s_b2l = s_b2h + 64 * BS;
    float*         s_bg  = (float*)(s_b2l + 64 * BS);
    float*         s_bo  = s_bg + 64;

    const int r    = blockIdx.y;
    const int s0   = blockIdx.x * 128;
    const int tid  = threadIdx.x;
    const int lane = tid & 31;
    const int w    = tid >> 5;
    const int g    = lane >> 2;      // 0..7
    const int tig  = lane & 3;       // 0..3

    // ---- stage B tiles (hi/lo split, transposed) ----
    const float* ov = g_ovec + r * 64;
    for (int idx = tid; idx < 4096; idx += 256) {
        int c = idx >> 6, j = idx & 63;            // wg[c][j], idx = c*64+j
        float x = __ldg(&wg[idx]);
        __nv_bfloat16 h1 = __float2bfloat16(x);
        s_b1h[j * BS + c] = h1;
        s_b1l[j * BS + c] = __float2bfloat16(x - __bfloat162float(h1));

        int jj = c, cc = j;                        // wo[jj][cc], idx = jj*64+cc
        float y = __ldg(&ov[jj]) * __ldg(&wo[idx]);
        __nv_bfloat16 h2 = __float2bfloat16(y);
        s_b2h[cc * BS + jj] = h2;
        s_b2l[cc * BS + jj] = __float2bfloat16(y - __bfloat162float(h2));
    }
    if (tid < 64) { s_bg[tid] = bg[tid]; s_bo[tid] = bo[tid]; }

    // ---- LayerNorm: warp per row (16 rows/warp), split into s_ah/s_al ----
    const float lw0 = ln_w[lane], lw1 = ln_w[lane + 32];
    const float lb0 = ln_b[lane], lb1 = ln_b[lane + 32];
    #pragma unroll
    for (int i = 0; i < 16; ++i) {
        const int row = w * 16 + i;
        const int s   = s0 + row;
        const float* mp = m + ((size_t)s * RDIM + r) * CDIM;
        float x0 = mp[lane];
        float x1 = mp[lane + 32];
        float sum = x0 + x1;
        #pragma unroll
        for (int o = 16; o; o >>= 1) sum += __shfl_xor_sync(0xffffffffu, sum, o);
        float mu = sum * (1.f / 64.f);
        float d0 = x0 - mu, d1 = x1 - mu;
        float vv = d0 * d0 + d1 * d1;
        #pragma unroll
        for (int o = 16; o; o >>= 1) vv += __shfl_xor_sync(0xffffffffu, vv, o);
        float rstd = rsqrtf(vv * (1.f / 64.f) + 1e-5f);
        float xn0 = d0 * rstd * lw0 + lb0;
        float xn1 = d1 * rstd * lw1 + lb1;
        __nv_bfloat16 h0 = __float2bfloat16(xn0);
        __nv_bfloat16 h1 = __float2bfloat16(xn1);
        s_ah[row * AS + lane]      = h0;
        s_ah[row * AS + lane + 32] = h1;
        s_al[row * AS + lane]      = __float2bfloat16(xn0 - __bfloat162float(h0));
        s_al[row * AS + lane + 32] = __float2bfloat16(xn1 - __bfloat162float(h1));
    }
    __syncthreads();

    const int ar0 = w * 16 + g;        // fragment rows ar0, ar0+8

    // ---- GEMM1: pre = XN @ wg ----
    float acc[8][4];
    #pragma unroll
    for (int nt = 0; nt < 8; ++nt)
        #pragma unroll
        for (int q = 0; q < 4; ++q) acc[nt][q] = 0.f;

    #pragma unroll
    for (int kk = 0; kk < 4; ++kk) {
        const int k0 = kk * 16 + tig * 2;
        uint32_t ah0 = ld32s(&s_ah[ar0 * AS + k0]);
        uint32_t ah1 = ld32s(&s_ah[(ar0 + 8) * AS + k0]);
        uint32_t ah2 = ld32s(&s_ah[ar0 * AS + k0 + 8]);
        uint32_t ah3 = ld32s(&s_ah[(ar0 + 8) * AS + k0 + 8]);
        uint32_t al0 = ld32s(&s_al[ar0 * AS + k0]);
        uint32_t al1 = ld32s(&s_al[(ar0 + 8) * AS + k0]);
        uint32_t al2 = ld32s(&s_al[ar0 * AS + k0 + 8]);
        uint32_t al3 = ld32s(&s_al[(ar0 + 8) * AS + k0 + 8]);
        #pragma unroll
        for (int nt = 0; nt < 8; ++nt) {
            const int n = nt * 8 + g;
            uint32_t bh0 = ld32s(&s_b1h[n * BS + k0]);
            uint32_t bh1 = ld32s(&s_b1h[n * BS + k0 + 8]);
            uint32_t bl0 = ld32s(&s_b1l[n * BS + k0]);
            uint32_t bl1 = ld32s(&s_b1l[n * BS + k0 + 8]);
            mma_bf16(acc[nt], ah0, ah1, ah2, ah3, bh0, bh1);
            mma_bf16(acc[nt], ah0, ah1, ah2, ah3, bl0, bl1);
            mma_bf16(acc[nt], al0, al1, al2, al3, bh0, bh1);
        }
    }
    __syncthreads();   // everyone done reading X tiles

    // ---- epilogue 1: sigmoid(pre + bg) -> G, split into s_ah/s_al ----
    #pragma unroll
    for (int nt = 0; nt < 8; ++nt) {
        const int col = nt * 8 + tig * 2;
        float v0 = sigm(acc[nt][0] + s_bg[col]);
        float v1 = sigm(acc[nt][1] + s_bg[col + 1]);
        float v2 = sigm(acc[nt][2] + s_bg[col]);
        float v3 = sigm(acc[nt][3] + s_bg[col + 1]);
        *(uint32_t*)&s_ah[ar0 * AS + col]       = pack_hi2(v0, v1);
        *(uint32_t*)&s_al[ar0 * AS + col]       = pack_lo2(v0, v1);
        *(uint32_t*)&s_ah[(ar0 + 8) * AS + col] = pack_hi2(v2, v3);
        *(uint32_t*)&s_al[(ar0 + 8) * AS + col] = pack_lo2(v2, v3);
    }
    __syncthreads();

    // ---- GEMM2: out = G @ (ov.*wo) + bo ----
    float acc2[8][4];
    #pragma unroll
    for (int nt = 0; nt < 8; ++nt)
        #pragma unroll
        for (int q = 0; q < 4; ++q) acc2[nt][q] = 0.f;

    #pragma unroll
    for (int kk = 0; kk < 4; ++kk) {
        const int k0 = kk * 16 + tig * 2;
        uint32_t ah0 = ld32s(&s_ah[ar0 * AS + k0]);
        uint32_t ah1 = ld32s(&s_ah[(ar0 + 8) * AS + k0]);
        uint32_t ah2 = ld32s(&s_ah[ar0 * AS + k0 + 8]);
        uint32_t ah3 = ld32s(&s_ah[(ar0 + 8) * AS + k0 + 8]);
        uint32_t al0 = ld32s(&s_al[ar0 * AS + k0]);
        uint32_t al1 = ld32s(&s_al[(ar0 + 8) * AS + k0]);
        uint32_t al2 = ld32s(&s_al[ar0 * AS + k0 + 8]);
        uint32_t al3 = ld32s(&s_al[(ar0 + 8) * AS + k0 + 8]);
        #pragma unroll
        for (int nt = 0; nt < 8; ++nt) {
            const int n = nt * 8 + g;
            uint32_t bh0 = ld32s(&s_b2h[n * BS + k0]);
            uint32_t bh1 = ld32s(&s_b2h[n * BS + k0 + 8]);
            uint32_t bl0 = ld32s(&s_b2l[n * BS + k0]);
            uint32_t bl1 = ld32s(&s_b2l[n * BS + k0 + 8]);
            mma_bf16(acc2[nt], ah0, ah1, ah2, ah3, bh0, bh1);
            mma_bf16(acc2[nt], ah0, ah1, ah2, ah3, bl0, bl1);
            mma_bf16(acc2[nt], al0, al1, al2, al3, bh0, bh1);
        }
    }

    // ---- final store: + bo ----
    {
        const int row0 = s0 + ar0;
        float* op0 = out + ((size_t)row0 * RDIM + r) * CDIM;
        float* op1 = out + ((size_t)(row0 + 8) * RDIM + r) * CDIM;
        #pragma unroll
        for (int nt = 0; nt < 8; ++nt) {
            const int col = nt * 8 + tig * 2;
            float b0 = s_bo[col], b1 = s_bo[col + 1];
            *(float2*)(op0 + col) = make_float2(acc2[nt][0] + b0, acc2[nt][1] + b1);
            *(float2*)(op1 + col) = make_float2(acc2[nt][2] + b0, acc2[nt][3] + b1);
        }
    }
}

// ---------------------------------------------------------------------
extern "C" void kernel_launch(void* const* d_in, const int* in_sizes, int n_in,
                              void* d_out, int out_size) {
    const float* m    = (const float*)d_in[0];
    const float* mask = (const float*)d_in[1];
    const float* ln_w = (const float*)d_in[2];
    const float* ln_b = (const float*)d_in[3];
    const float* wq   = (const float*)d_in[4];
    const float* wk   = (const float*)d_in[5];
    const float* wv   = (const float*)d_in[6];
    const float* wg   = (const float*)d_in[7];
    const float* bg   = (const float*)d_in[8];
    const float* wo   = (const float*)d_in[9];
    const float* bo   = (const float*)d_in[10];
    float* out = (float*)d_out;

    cudaFuncSetAttribute(k_out_mma, cudaFuncAttributeMaxDynamicSharedMemorySize, SMC_BYTES);

    dim3 gA(NSBLK, RDIM);
    k_pool_kv<<<gA, 256>>>(m, mask, ln_w, ln_b, wk, wv);
    k_attn<<<RDIM, 256>>>(mask, wq);
    dim3 gC(SDIM / 128, RDIM);
    k_out_mma<<<gC, 256, SMC_BYTES>>>(m, ln_w, ln_b, wg, bg, wo, bo, out);
}